// round 11
// baseline (speedup 1.0000x reference)
#include <cuda_runtime.h>
#include <cuda_fp16.h>
#include <cstdint>

// QuantizedCodebook (VQ-VAE): N=131072 rows, D=64, K=512.
// out layout (confirmed): [loss(1) | quantize(N*D) | indices(N)] fp32.
// fp16 double-split mma (m16n8k16), single pass; 2 row-subtiles per warp:
// each B load feeds both subtiles (85 B/mma), 6 independent mma chains/warp.
//   x.c ~= h1.c1 + h2.c1 + h1.c2  (error ~ xc*2^-22; rel_err 0.0 in R10)

#define KCODES 512
#define DDIM   64
#define TPB    384
#define NWARP  (TPB / 32)
#define P128   514          // ulonglong2 row pitch (512 + 2 pad): conflict-free LDS.128
#define MAXBLK 512

typedef uint32_t u32;
typedef unsigned long long u64;

__device__ double   g_partials[MAXBLK];
__device__ unsigned g_done;           // zero-init; last block resets each run

__device__ __forceinline__ u32 pack_h2(float lo, float hi) {
    u32 r; asm("cvt.rn.f16x2.f32 %0, %1, %2;" : "=r"(r) : "f"(hi), "f"(lo));
    return r;
}
__device__ __forceinline__ float f16_residual(float v) {
    return v - __half2float(__float2half_rn(v));
}
__device__ __forceinline__ void mma_f16(float c[4], const u32 a[4], u32 b0, u32 b1) {
    asm("mma.sync.aligned.m16n8k16.row.col.f32.f16.f16.f32 "
        "{%0,%1,%2,%3}, {%4,%5,%6,%7}, {%8,%9}, {%0,%1,%2,%3};"
        : "+f"(c[0]), "+f"(c[1]), "+f"(c[2]), "+f"(c[3])
        : "r"(a[0]), "r"(a[1]), "r"(a[2]), "r"(a[3]), "r"(b0), "r"(b1));
}

__global__ void __launch_bounds__(TPB, 1)
vq_kernel(const float* __restrict__ x, const float* __restrict__ cb,
          float* __restrict__ out, int nrows)
{
    // dynamic smem: BQ[16][P128] ulonglong2 (131.6 KB) | scq[512] float
    // BQ[(4*t4+q)][c] = { u64(b0c1 | b1c1<<32), u64(b0c2 | b1c2<<32) }
    extern __shared__ unsigned char smraw[];
    ulonglong2* BQ  = (ulonglong2*)smraw;
    float*      scq = (float*)(smraw + 16 * P128 * sizeof(ulonglong2));
    __shared__ int sidx[NWARP][32];

    float* out_q   = out + 1;
    float* out_idx = out + 1 + (size_t)nrows * DDIM;

    const int tid  = threadIdx.x;
    const int w    = tid >> 5;
    const int lane = tid & 31;
    const int g4   = lane >> 2;   // groupID 0..7
    const int q    = lane & 3;    // threadID-in-group 0..3

    // ---- ||c||^2 (exact fp32) ----
    for (int c = tid; c < KCODES; c += TPB) {
        const float* cr = cb + c * DDIM;
        float s = 0.f;
        #pragma unroll
        for (int i = 0; i < DDIM; i++) s = fmaf(cr[i], cr[i], s);
        scq[c] = s;
    }

    // ---- stage codebook: f16 split, fragment-packed 16B records ----
    for (int idx = tid; idx < 16 * KCODES; idx += TPB) {
        int row = idx >> 9;          // 4*t4+q, 0..15
        int c   = idx & (KCODES - 1);
        int t4  = row >> 2, qq = row & 3;
        int k0  = 16 * t4 + 2 * qq;
        const float* src = cb + (size_t)c * DDIM;
        float v0 = src[k0],     v1 = src[k0 + 1];
        float v2 = src[k0 + 8], v3 = src[k0 + 9];
        u32 b0c1 = pack_h2(v0, v1);
        u32 b1c1 = pack_h2(v2, v3);
        u32 b0c2 = pack_h2(f16_residual(v0), f16_residual(v1));
        u32 b1c2 = pack_h2(f16_residual(v2), f16_residual(v3));
        ulonglong2 val;
        val.x = (u64)b0c1 | ((u64)b1c1 << 32);
        val.y = (u64)b0c2 | ((u64)b1c2 << 32);
        BQ[(size_t)row * P128 + c] = val;
    }
    __syncthreads();

    // ---- row-group split: groups of 32 rows ----
    const int ng = nrows >> 5;                               // 4096
    const int gs = (int)(((long long)blockIdx.x * ng) / gridDim.x);
    const int ge = (int)(((long long)(blockIdx.x + 1) * ng) / gridDim.x);

    float lsum = 0.f;

    #pragma unroll 1
    for (int g = gs + w; g < ge; g += NWARP) {
        const int R = g << 5;     // 32 rows per group

        // ---- A fragments, 2 subtiles: a1=f16(x), a2=f16(x-f16(x)); 64 regs ----
        u32 a1[2][4][4], a2[2][4][4];
        #pragma unroll
        for (int s = 0; s < 2; s++)
            #pragma unroll
            for (int t4 = 0; t4 < 4; t4++)
                #pragma unroll
                for (int rg = 0; rg < 4; rg++) {
                    int row = R + 16 * s + g4 + (rg & 1) * 8;
                    int col = 16 * t4 + 2 * q + (rg >> 1) * 8;
                    float2 v = *(const float2*)(x + (size_t)row * DDIM + col);
                    a1[s][t4][rg] = pack_h2(v.x, v.y);
                    a2[s][t4][rg] = pack_h2(f16_residual(v.x), f16_residual(v.y));
                }

        float best[4] = {3.402823466e38f, 3.402823466e38f,
                         3.402823466e38f, 3.402823466e38f};
        int   bx[4]   = {0, 0, 0, 0};

        // ---- n-tiles: 8 codes; 4 LDS.128 shared by 24 mma (6 indep chains) ----
        #pragma unroll 1
        for (int n = 0; n < KCODES / 8; n++) {
            float c1a[2][4] = {{0.f,0.f,0.f,0.f},{0.f,0.f,0.f,0.f}};  // h1.c1
            float c2a[2][4] = {{0.f,0.f,0.f,0.f},{0.f,0.f,0.f,0.f}};  // h2.c1
            float c3a[2][4] = {{0.f,0.f,0.f,0.f},{0.f,0.f,0.f,0.f}};  // h1.c2
            const ulonglong2* bp = BQ + 8 * n + g4;
            #pragma unroll
            for (int t4 = 0; t4 < 4; t4++) {
                ulonglong2 v = bp[(size_t)(4 * t4 + q) * P128];
                u32 b0 = (u32)v.x, b1 = (u32)(v.x >> 32);
                u32 d0 = (u32)v.y, d1 = (u32)(v.y >> 32);
                mma_f16(c1a[0], a1[0][t4], b0, b1);
                mma_f16(c1a[1], a1[1][t4], b0, b1);
                mma_f16(c2a[0], a2[0][t4], b0, b1);
                mma_f16(c2a[1], a2[1][t4], b0, b1);
                mma_f16(c3a[0], a1[0][t4], d0, d1);
                mma_f16(c3a[1], a1[1][t4], d0, d1);
            }
            int code0 = 8 * n + 2 * q;
            float2 sq = *(const float2*)(scq + code0);
            #pragma unroll
            for (int s = 0; s < 2; s++) {
                float d;
                d = fmaf(-2.f, c1a[s][0] + c2a[s][0] + c3a[s][0], sq.x);
                if (d < best[2*s])   { best[2*s]   = d; bx[2*s]   = code0; }
                d = fmaf(-2.f, c1a[s][1] + c2a[s][1] + c3a[s][1], sq.y);
                if (d < best[2*s])   { best[2*s]   = d; bx[2*s]   = code0 + 1; }
                d = fmaf(-2.f, c1a[s][2] + c2a[s][2] + c3a[s][2], sq.x);
                if (d < best[2*s+1]) { best[2*s+1] = d; bx[2*s+1] = code0; }
                d = fmaf(-2.f, c1a[s][3] + c2a[s][3] + c3a[s][3], sq.y);
                if (d < best[2*s+1]) { best[2*s+1] = d; bx[2*s+1] = code0 + 1; }
            }
        }

        // ---- quad reduce (lanes differing in q), first-index tie ----
        #pragma unroll
        for (int j = 0; j < 4; j++) {
            #pragma unroll
            for (int off = 1; off <= 2; off <<= 1) {
                float ob = __shfl_xor_sync(0xffffffffu, best[j], off);
                int   oi = __shfl_xor_sync(0xffffffffu, bx[j], off);
                if (ob < best[j] || (ob == best[j] && oi < bx[j])) {
                    best[j] = ob; bx[j] = oi;
                }
            }
        }

        if (q == 0) {
            #pragma unroll
            for (int s = 0; s < 2; s++) {
                int r0 = R + 16 * s + g4, r1 = R + 16 * s + 8 + g4;
                out_idx[r0] = (float)bx[2*s];     sidx[w][16*s + g4]     = bx[2*s];
                out_idx[r1] = (float)bx[2*s + 1]; sidx[w][16*s + 8 + g4] = bx[2*s+1];
            }
        }
        __syncwarp();

        // ---- exact fp32 quantize + loss (2 dims/lane) ----
        #pragma unroll 1
        for (int r = 0; r < 32; r++) {
            int bi  = sidx[w][r];
            int row = R + r;
            float2 xv = *(const float2*)(x  + (size_t)row * DDIM + 2 * lane);
            float2 cv = *(const float2*)(cb + (size_t)bi  * DDIM + 2 * lane);
            float o0 = xv.x + (cv.x - xv.x);
            float o1 = xv.y + (cv.y - xv.y);
            float t0 = o0 - xv.x; lsum = fmaf(t0, t0, lsum);
            float t1 = o1 - xv.y; lsum = fmaf(t1, t1, lsum);
            float* oq = out_q + (size_t)row * DDIM + 2 * lane;
            oq[0] = o0;   // out_q only 4B-aligned: scalar stores
            oq[1] = o1;
        }
    }

    // ---- loss: block reduce -> double partial; last block finalizes ----
    __shared__ float warp_sums[NWARP];
    #pragma unroll
    for (int off = 16; off; off >>= 1)
        lsum += __shfl_down_sync(0xffffffffu, lsum, off);
    if (lane == 0) warp_sums[w] = lsum;
    __syncthreads();
    if (tid == 0) {
        float b = 0.f;
        #pragma unroll
        for (int i = 0; i < NWARP; i++) b += warp_sums[i];
        g_partials[blockIdx.x] = (double)b;
        __threadfence();
        unsigned done = atomicAdd(&g_done, 1u);
        if (done == gridDim.x - 1) {
            double total = 0.0;
            for (int k = 0; k < gridDim.x; k++) total += g_partials[k];
            out[0] = (float)(total * 1.25 / ((double)nrows * DDIM));
            __threadfence();
            g_done = 0;   // self-reset for graph replay
        }
    }
}

extern "C" void kernel_launch(void* const* d_in, const int* in_sizes, int n_in,
                              void* d_out, int out_size)
{
    const float* x  = (const float*)d_in[0];   // inputs  [128,32,32,64]
    const float* cb = (const float*)d_in[1];   // codebook [512,64]
    const int n_elem = in_sizes[0];            // 8388608
    const int nrows  = n_elem / DDIM;          // 131072

    const int smem_bytes = 16 * P128 * (int)sizeof(ulonglong2) + KCODES * 4;
    cudaFuncSetAttribute(vq_kernel,
                         cudaFuncAttributeMaxDynamicSharedMemorySize, smem_bytes);

    int sms = 148;
    cudaDeviceGetAttribute(&sms, cudaDevAttrMultiProcessorCount, 0);
    if (sms > MAXBLK) sms = MAXBLK;

    vq_kernel<<<sms, TPB, smem_bytes>>>(x, cb, (float*)d_out, nrows);
}

// round 13
// speedup vs baseline: 1.1060x; 1.1060x over previous
#include <cuda_runtime.h>
#include <cuda_fp16.h>
#include <cstdint>

// QuantizedCodebook (VQ-VAE): N=131072 rows, D=64, K=512.
// out layout (confirmed): [loss(1) | quantize(N*D) | indices(N)] fp32.
// fp16 double-split mma (m16n8k16), single pass; 2 row-subtiles per warp
// (each B load feeds 24 mma, 6 independent chains) at 4 warps/SMSP.
//   x.c ~= h1.c1 + h2.c1 + h1.c2  (error ~ xc*2^-22; rel_err 0.0 in R10/R11)

#define KCODES 512
#define DDIM   64
#define TPB    512
#define NWARP  (TPB / 32)
#define P128   514          // ulonglong2 row pitch (512 + 2 pad): conflict-free LDS.128
#define MAXBLK 512

typedef uint32_t u32;
typedef unsigned long long u64;

__device__ double   g_partials[MAXBLK];
__device__ unsigned g_done;           // zero-init; last block resets each run

__device__ __forceinline__ u32 pack_h2(float lo, float hi) {
    u32 r; asm("cvt.rn.f16x2.f32 %0, %1, %2;" : "=r"(r) : "f"(hi), "f"(lo));
    return r;
}
__device__ __forceinline__ float f16_residual(float v) {
    return v - __half2float(__float2half_rn(v));
}
__device__ __forceinline__ void mma_f16(float c[4], const u32 a[4], u32 b0, u32 b1) {
    asm("mma.sync.aligned.m16n8k16.row.col.f32.f16.f16.f32 "
        "{%0,%1,%2,%3}, {%4,%5,%6,%7}, {%8,%9}, {%0,%1,%2,%3};"
        : "+f"(c[0]), "+f"(c[1]), "+f"(c[2]), "+f"(c[3])
        : "r"(a[0]), "r"(a[1]), "r"(a[2]), "r"(a[3]), "r"(b0), "r"(b1));
}

__global__ void __launch_bounds__(TPB, 1)
vq_kernel(const float* __restrict__ x, const float* __restrict__ cb,
          float* __restrict__ out, int nrows)
{
    // dynamic smem: BQ[16][P128] ulonglong2 (131.6 KB) | scq[512] float
    // BQ[(4*t4+q)][c] = { u64(b0c1 | b1c1<<32), u64(b0c2 | b1c2<<32) }
    extern __shared__ unsigned char smraw[];
    ulonglong2* BQ  = (ulonglong2*)smraw;
    float*      scq = (float*)(smraw + 16 * P128 * sizeof(ulonglong2));
    __shared__ int sidx[NWARP][32];

    float* out_q   = out + 1;
    float* out_idx = out + 1 + (size_t)nrows * DDIM;

    const int tid  = threadIdx.x;
    const int w    = tid >> 5;
    const int lane = tid & 31;
    const int g4   = lane >> 2;   // groupID 0..7
    const int q    = lane & 3;    // threadID-in-group 0..3

    // ---- ||c||^2 (exact fp32) ----
    for (int c = tid; c < KCODES; c += TPB) {
        const float* cr = cb + c * DDIM;
        float s = 0.f;
        #pragma unroll
        for (int i = 0; i < DDIM; i++) s = fmaf(cr[i], cr[i], s);
        scq[c] = s;
    }

    // ---- stage codebook: f16 split, fragment-packed 16B records ----
    for (int idx = tid; idx < 16 * KCODES; idx += TPB) {
        int row = idx >> 9;          // 4*t4+q, 0..15
        int c   = idx & (KCODES - 1);
        int t4  = row >> 2, qq = row & 3;
        int k0  = 16 * t4 + 2 * qq;
        const float* src = cb + (size_t)c * DDIM;
        float v0 = src[k0],     v1 = src[k0 + 1];
        float v2 = src[k0 + 8], v3 = src[k0 + 9];
        u32 b0c1 = pack_h2(v0, v1);
        u32 b1c1 = pack_h2(v2, v3);
        u32 b0c2 = pack_h2(f16_residual(v0), f16_residual(v1));
        u32 b1c2 = pack_h2(f16_residual(v2), f16_residual(v3));
        ulonglong2 val;
        val.x = (u64)b0c1 | ((u64)b1c1 << 32);
        val.y = (u64)b0c2 | ((u64)b1c2 << 32);
        BQ[(size_t)row * P128 + c] = val;
    }
    __syncthreads();

    // ---- row-group split: groups of 32 rows ----
    const int ng = nrows >> 5;                               // 4096
    const int gs = (int)(((long long)blockIdx.x * ng) / gridDim.x);
    const int ge = (int)(((long long)(blockIdx.x + 1) * ng) / gridDim.x);

    float lsum = 0.f;

    #pragma unroll 1
    for (int g = gs + w; g < ge; g += NWARP) {
        const int R = g << 5;     // 32 rows per group

        // ---- A fragments, 2 subtiles: a1=f16(x), a2=f16(x-f16(x)); 64 regs ----
        u32 a1[2][4][4], a2[2][4][4];
        #pragma unroll
        for (int s = 0; s < 2; s++)
            #pragma unroll
            for (int t4 = 0; t4 < 4; t4++)
                #pragma unroll
                for (int rg = 0; rg < 4; rg++) {
                    int row = R + 16 * s + g4 + (rg & 1) * 8;
                    int col = 16 * t4 + 2 * q + (rg >> 1) * 8;
                    float2 v = *(const float2*)(x + (size_t)row * DDIM + col);
                    a1[s][t4][rg] = pack_h2(v.x, v.y);
                    a2[s][t4][rg] = pack_h2(f16_residual(v.x), f16_residual(v.y));
                }

        float best[4] = {3.402823466e38f, 3.402823466e38f,
                         3.402823466e38f, 3.402823466e38f};
        int   bx[4]   = {0, 0, 0, 0};

        // ---- n-tiles: 8 codes; 4 LDS.128 shared by 24 mma (6 indep chains) ----
        #pragma unroll 1
        for (int n = 0; n < KCODES / 8; n++) {
            float c1a[2][4] = {{0.f,0.f,0.f,0.f},{0.f,0.f,0.f,0.f}};  // h1.c1
            float c2a[2][4] = {{0.f,0.f,0.f,0.f},{0.f,0.f,0.f,0.f}};  // h2.c1
            float c3a[2][4] = {{0.f,0.f,0.f,0.f},{0.f,0.f,0.f,0.f}};  // h1.c2
            const ulonglong2* bp = BQ + 8 * n + g4;
            #pragma unroll
            for (int t4 = 0; t4 < 4; t4++) {
                ulonglong2 v = bp[(size_t)(4 * t4 + q) * P128];
                u32 b0 = (u32)v.x, b1 = (u32)(v.x >> 32);
                u32 d0 = (u32)v.y, d1 = (u32)(v.y >> 32);
                mma_f16(c1a[0], a1[0][t4], b0, b1);
                mma_f16(c1a[1], a1[1][t4], b0, b1);
                mma_f16(c2a[0], a2[0][t4], b0, b1);
                mma_f16(c2a[1], a2[1][t4], b0, b1);
                mma_f16(c3a[0], a1[0][t4], d0, d1);
                mma_f16(c3a[1], a1[1][t4], d0, d1);
            }
            int code0 = 8 * n + 2 * q;
            float2 sq = *(const float2*)(scq + code0);
            #pragma unroll
            for (int s = 0; s < 2; s++) {
                float d;
                d = fmaf(-2.f, c1a[s][0] + c2a[s][0] + c3a[s][0], sq.x);
                if (d < best[2*s])   { best[2*s]   = d; bx[2*s]   = code0; }
                d = fmaf(-2.f, c1a[s][1] + c2a[s][1] + c3a[s][1], sq.y);
                if (d < best[2*s])   { best[2*s]   = d; bx[2*s]   = code0 + 1; }
                d = fmaf(-2.f, c1a[s][2] + c2a[s][2] + c3a[s][2], sq.x);
                if (d < best[2*s+1]) { best[2*s+1] = d; bx[2*s+1] = code0; }
                d = fmaf(-2.f, c1a[s][3] + c2a[s][3] + c3a[s][3], sq.y);
                if (d < best[2*s+1]) { best[2*s+1] = d; bx[2*s+1] = code0 + 1; }
            }
        }

        // ---- quad reduce (lanes differing in q), first-index tie ----
        #pragma unroll
        for (int j = 0; j < 4; j++) {
            #pragma unroll
            for (int off = 1; off <= 2; off <<= 1) {
                float ob = __shfl_xor_sync(0xffffffffu, best[j], off);
                int   oi = __shfl_xor_sync(0xffffffffu, bx[j], off);
                if (ob < best[j] || (ob == best[j] && oi < bx[j])) {
                    best[j] = ob; bx[j] = oi;
                }
            }
        }

        if (q == 0) {
            #pragma unroll
            for (int s = 0; s < 2; s++) {
                int r0 = R + 16 * s + g4, r1 = R + 16 * s + 8 + g4;
                out_idx[r0] = (float)bx[2*s];     sidx[w][16*s + g4]     = bx[2*s];
                out_idx[r1] = (float)bx[2*s + 1]; sidx[w][16*s + 8 + g4] = bx[2*s+1];
            }
        }
        __syncwarp();

        // ---- exact fp32 quantize + loss, MLP-unrolled 4 rows at a time ----
        #pragma unroll 1
        for (int r0 = 0; r0 < 32; r0 += 4) {
            int    bis[4];
            float2 xvv[4], cvv[4];
            #pragma unroll
            for (int j = 0; j < 4; j++) {
                int row = R + r0 + j;
                bis[j]  = sidx[w][r0 + j];
                xvv[j]  = *(const float2*)(x  + (size_t)row    * DDIM + 2 * lane);
                cvv[j]  = *(const float2*)(cb + (size_t)bis[j] * DDIM + 2 * lane);
            }
            #pragma unroll
            for (int j = 0; j < 4; j++) {
                int row = R + r0 + j;
                float o0 = xvv[j].x + (cvv[j].x - xvv[j].x);
                float o1 = xvv[j].y + (cvv[j].y - xvv[j].y);
                float t0 = o0 - xvv[j].x; lsum = fmaf(t0, t0, lsum);
                float t1 = o1 - xvv[j].y; lsum = fmaf(t1, t1, lsum);
                float* oq = out_q + (size_t)row * DDIM + 2 * lane;
                oq[0] = o0;   // out_q only 4B-aligned: scalar stores
                oq[1] = o1;
            }
        }
    }

    // ---- loss: block reduce -> double partial; last block finalizes ----
    __shared__ float warp_sums[NWARP];
    #pragma unroll
    for (int off = 16; off; off >>= 1)
        lsum += __shfl_down_sync(0xffffffffu, lsum, off);
    if (lane == 0) warp_sums[w] = lsum;
    __syncthreads();
    if (tid == 0) {
        float b = 0.f;
        #pragma unroll
        for (int i = 0; i < NWARP; i++) b += warp_sums[i];
        g_partials[blockIdx.x] = (double)b;
        __threadfence();
        unsigned done = atomicAdd(&g_done, 1u);
        if (done == gridDim.x - 1) {
            double total = 0.0;
            for (int k = 0; k < gridDim.x; k++) total += g_partials[k];
            out[0] = (float)(total * 1.25 / ((double)nrows * DDIM));
            __threadfence();
            g_done = 0;   // self-reset for graph replay
        }
    }
}

extern "C" void kernel_launch(void* const* d_in, const int* in_sizes, int n_in,
                              void* d_out, int out_size)
{
    const float* x  = (const float*)d_in[0];   // inputs  [128,32,32,64]
    const float* cb = (const float*)d_in[1];   // codebook [512,64]
    const int n_elem = in_sizes[0];            // 8388608
    const int nrows  = n_elem / DDIM;          // 131072

    const int smem_bytes = 16 * P128 * (int)sizeof(ulonglong2) + KCODES * 4;
    cudaFuncSetAttribute(vq_kernel,
                         cudaFuncAttributeMaxDynamicSharedMemorySize, smem_bytes);

    int sms = 148;
    cudaDeviceGetAttribute(&sms, cudaDevAttrMultiProcessorCount, 0);
    if (sms > MAXBLK) sms = MAXBLK;

    vq_kernel<<<sms, TPB, smem_bytes>>>(x, cb, (float*)d_out, nrows);
}

// round 14
// speedup vs baseline: 1.2013x; 1.0862x over previous
#include <cuda_runtime.h>
#include <cuda_fp16.h>
#include <cstdint>

// QuantizedCodebook (VQ-VAE): N=131072 rows, D=64, K=512.
// out layout (confirmed): [loss(1) | quantize(N*D) | indices(N)] fp32.
// fp16 double-split mma (m16n8k16), single pass; M=16 rows/warp at
// 6 warps/SMSP (TPB=768, regs capped to 85 by launch_bounds).
//   x.c ~= h1.c1 + h2.c1 + h1.c2  (error ~ xc*2^-22; rel_err 0.0 since R10)

#define KCODES 512
#define DDIM   64
#define TPB    768
#define NWARP  (TPB / 32)
#define P128   514          // ulonglong2 row pitch (512 + 2 pad): conflict-free LDS.128
#define MAXBLK 512

typedef uint32_t u32;
typedef unsigned long long u64;

__device__ double   g_partials[MAXBLK];
__device__ unsigned g_done;           // zero-init; last block resets each run

__device__ __forceinline__ u32 pack_h2(float lo, float hi) {
    u32 r; asm("cvt.rn.f16x2.f32 %0, %1, %2;" : "=r"(r) : "f"(hi), "f"(lo));
    return r;
}
__device__ __forceinline__ float f16_residual(float v) {
    return v - __half2float(__float2half_rn(v));
}
__device__ __forceinline__ void mma_f16(float c[4], const u32 a[4], u32 b0, u32 b1) {
    asm("mma.sync.aligned.m16n8k16.row.col.f32.f16.f16.f32 "
        "{%0,%1,%2,%3}, {%4,%5,%6,%7}, {%8,%9}, {%0,%1,%2,%3};"
        : "+f"(c[0]), "+f"(c[1]), "+f"(c[2]), "+f"(c[3])
        : "r"(a[0]), "r"(a[1]), "r"(a[2]), "r"(a[3]), "r"(b0), "r"(b1));
}

__global__ void __launch_bounds__(TPB, 1)
vq_kernel(const float* __restrict__ x, const float* __restrict__ cb,
          float* __restrict__ out, int nrows)
{
    // dynamic smem: BQ[16][P128] ulonglong2 (131.6 KB) | scq[512] float
    // BQ[(4*t4+q)][c] = { u64(b0c1 | b1c1<<32), u64(b0c2 | b1c2<<32) }
    extern __shared__ unsigned char smraw[];
    ulonglong2* BQ  = (ulonglong2*)smraw;
    float*      scq = (float*)(smraw + 16 * P128 * sizeof(ulonglong2));
    __shared__ int sidx[NWARP][16];

    float* out_q   = out + 1;
    float* out_idx = out + 1 + (size_t)nrows * DDIM;

    const int tid  = threadIdx.x;
    const int w    = tid >> 5;
    const int lane = tid & 31;
    const int g4   = lane >> 2;   // groupID 0..7
    const int q    = lane & 3;    // threadID-in-group 0..3

    // ---- ||c||^2 (exact fp32) ----
    for (int c = tid; c < KCODES; c += TPB) {
        const float* cr = cb + c * DDIM;
        float s = 0.f;
        #pragma unroll
        for (int i = 0; i < DDIM; i++) s = fmaf(cr[i], cr[i], s);
        scq[c] = s;
    }

    // ---- stage codebook: f16 split, fragment-packed 16B records ----
    for (int idx = tid; idx < 16 * KCODES; idx += TPB) {
        int row = idx >> 9;          // 4*t4+q, 0..15
        int c   = idx & (KCODES - 1);
        int t4  = row >> 2, qq = row & 3;
        int k0  = 16 * t4 + 2 * qq;
        const float* src = cb + (size_t)c * DDIM;
        float v0 = src[k0],     v1 = src[k0 + 1];
        float v2 = src[k0 + 8], v3 = src[k0 + 9];
        u32 b0c1 = pack_h2(v0, v1);
        u32 b1c1 = pack_h2(v2, v3);
        u32 b0c2 = pack_h2(f16_residual(v0), f16_residual(v1));
        u32 b1c2 = pack_h2(f16_residual(v2), f16_residual(v3));
        ulonglong2 val;
        val.x = (u64)b0c1 | ((u64)b1c1 << 32);
        val.y = (u64)b0c2 | ((u64)b1c2 << 32);
        BQ[(size_t)row * P128 + c] = val;
    }
    __syncthreads();

    // ---- row-group split: groups of 16 rows ----
    const int ng = nrows >> 4;                               // 8192
    const int gs = (int)(((long long)blockIdx.x * ng) / gridDim.x);
    const int ge = (int)(((long long)(blockIdx.x + 1) * ng) / gridDim.x);

    float lsum = 0.f;

    #pragma unroll 1
    for (int g = gs + w; g < ge; g += NWARP) {
        const int R = g << 4;     // 16 rows per group

        // ---- A fragments: a1 = f16(x), a2 = f16(x - f16(x)); 32 regs ----
        u32 a1[4][4], a2[4][4];
        #pragma unroll
        for (int t4 = 0; t4 < 4; t4++)
            #pragma unroll
            for (int rg = 0; rg < 4; rg++) {
                int row = R + g4 + (rg & 1) * 8;
                int col = 16 * t4 + 2 * q + (rg >> 1) * 8;
                float2 v = *(const float2*)(x + (size_t)row * DDIM + col);
                a1[t4][rg] = pack_h2(v.x, v.y);
                a2[t4][rg] = pack_h2(f16_residual(v.x), f16_residual(v.y));
            }

        const int rows0 = R + g4, rows1 = R + 8 + g4;

        float best[2] = {3.402823466e38f, 3.402823466e38f};
        int   bx[2]   = {0, 0};

        // ---- n-tiles: 8 codes each; 4 LDS.128 + 12 mma (3 indep chains) ----
        #pragma unroll 2
        for (int n = 0; n < KCODES / 8; n++) {
            float c1a[4] = {0.f, 0.f, 0.f, 0.f};   // h1 . c1
            float c2a[4] = {0.f, 0.f, 0.f, 0.f};   // h2 . c1
            float c3a[4] = {0.f, 0.f, 0.f, 0.f};   // h1 . c2
            const ulonglong2* bp = BQ + 8 * n + g4;
            #pragma unroll
            for (int t4 = 0; t4 < 4; t4++) {
                ulonglong2 v = bp[(size_t)(4 * t4 + q) * P128];
                u32 b0 = (u32)v.x, b1 = (u32)(v.x >> 32);
                u32 d0 = (u32)v.y, d1 = (u32)(v.y >> 32);
                mma_f16(c1a, a1[t4], b0, b1);
                mma_f16(c2a, a2[t4], b0, b1);
                mma_f16(c3a, a1[t4], d0, d1);
            }
            int code0 = 8 * n + 2 * q;
            float2 sq = *(const float2*)(scq + code0);
            float d;
            d = fmaf(-2.f, c1a[0] + c2a[0] + c3a[0], sq.x);
            if (d < best[0]) { best[0] = d; bx[0] = code0; }
            d = fmaf(-2.f, c1a[1] + c2a[1] + c3a[1], sq.y);
            if (d < best[0]) { best[0] = d; bx[0] = code0 + 1; }
            d = fmaf(-2.f, c1a[2] + c2a[2] + c3a[2], sq.x);
            if (d < best[1]) { best[1] = d; bx[1] = code0; }
            d = fmaf(-2.f, c1a[3] + c2a[3] + c3a[3], sq.y);
            if (d < best[1]) { best[1] = d; bx[1] = code0 + 1; }
        }

        // ---- quad reduce (lanes differing in q), first-index tie ----
        #pragma unroll
        for (int j = 0; j < 2; j++) {
            #pragma unroll
            for (int off = 1; off <= 2; off <<= 1) {
                float ob = __shfl_xor_sync(0xffffffffu, best[j], off);
                int   oi = __shfl_xor_sync(0xffffffffu, bx[j], off);
                if (ob < best[j] || (ob == best[j] && oi < bx[j])) {
                    best[j] = ob; bx[j] = oi;
                }
            }
        }

        if (q == 0) {
            out_idx[rows0] = (float)bx[0]; sidx[w][g4]     = bx[0];
            out_idx[rows1] = (float)bx[1]; sidx[w][g4 + 8] = bx[1];
        }
        __syncwarp();

        // ---- exact fp32 quantize + loss, MLP-batched 4 rows at a time ----
        #pragma unroll 1
        for (int r0 = 0; r0 < 16; r0 += 4) {
            int    bis[4];
            float2 xvv[4], cvv[4];
            #pragma unroll
            for (int j = 0; j < 4; j++) {
                int row = R + r0 + j;
                bis[j]  = sidx[w][r0 + j];
                xvv[j]  = *(const float2*)(x  + (size_t)row    * DDIM + 2 * lane);
                cvv[j]  = *(const float2*)(cb + (size_t)bis[j] * DDIM + 2 * lane);
            }
            #pragma unroll
            for (int j = 0; j < 4; j++) {
                int row = R + r0 + j;
                float o0 = xvv[j].x + (cvv[j].x - xvv[j].x);
                float o1 = xvv[j].y + (cvv[j].y - xvv[j].y);
                float t0 = o0 - xvv[j].x; lsum = fmaf(t0, t0, lsum);
                float t1 = o1 - xvv[j].y; lsum = fmaf(t1, t1, lsum);
                float* oq = out_q + (size_t)row * DDIM + 2 * lane;
                oq[0] = o0;   // out_q only 4B-aligned: scalar stores
                oq[1] = o1;
            }
        }
    }

    // ---- loss: block reduce -> double partial; last block finalizes ----
    __shared__ float warp_sums[NWARP];
    #pragma unroll
    for (int off = 16; off; off >>= 1)
        lsum += __shfl_down_sync(0xffffffffu, lsum, off);
    if (lane == 0) warp_sums[w] = lsum;
    __syncthreads();
    if (tid == 0) {
        float b = 0.f;
        #pragma unroll
        for (int i = 0; i < NWARP; i++) b += warp_sums[i];
        g_partials[blockIdx.x] = (double)b;
        __threadfence();
        unsigned done = atomicAdd(&g_done, 1u);
        if (done == gridDim.x - 1) {
            double total = 0.0;
            for (int k = 0; k < gridDim.x; k++) total += g_partials[k];
            out[0] = (float)(total * 1.25 / ((double)nrows * DDIM));
            __threadfence();
            g_done = 0;   // self-reset for graph replay
        }
    }
}

extern "C" void kernel_launch(void* const* d_in, const int* in_sizes, int n_in,
                              void* d_out, int out_size)
{
    const float* x  = (const float*)d_in[0];   // inputs  [128,32,32,64]
    const float* cb = (const float*)d_in[1];   // codebook [512,64]
    const int n_elem = in_sizes[0];            // 8388608
    const int nrows  = n_elem / DDIM;          // 131072

    const int smem_bytes = 16 * P128 * (int)sizeof(ulonglong2) + KCODES * 4;
    cudaFuncSetAttribute(vq_kernel,
                         cudaFuncAttributeMaxDynamicSharedMemorySize, smem_bytes);

    int sms = 148;
    cudaDeviceGetAttribute(&sms, cudaDevAttrMultiProcessorCount, 0);
    if (sms > MAXBLK) sms = MAXBLK;

    vq_kernel<<<sms, TPB, smem_bytes>>>(x, cb, (float*)d_out, nrows);
}